// round 7
// baseline (speedup 1.0000x reference)
#include <cuda_runtime.h>
#include <cuda_bf16.h>
#include <cstdint>

#define NN 100000
#define NE 1600000
#define IND 128
#define HID 32
#define OUTD 64
#define NCOL 288   // 8*32 + 32 (root)
#define NB_SCAN 98 // ceil(NN/1024)

// -------- scratch (static device memory; 16B-aligned) --------
__device__ __align__(16) float g_wcat[IND * NCOL];
__device__ __align__(16) float g_xr[(size_t)NN * IND];
__device__ __align__(16) float g_y1[(size_t)NN * NCOL];
__device__ __align__(16) float g_agg1[NN * HID];
__device__ __align__(16) float g_deg[NN];
__device__ __align__(16) float g_h[NN * HID];
__device__ __align__(16) float g_y2[NN * 16];
__device__ __align__(16) float g_W2p[512];
__device__ __align__(16) float g_r2p[64];
__device__ __align__(16) float g_bp[2];
__device__ int g_is64;
__device__ int g_cnt[NN];
__device__ int g_off[NN + 1];
__device__ int g_pos[NN];
__device__ int g_bsum[128];
__device__ int g_boff[128];
__device__ int g_epack[NE];   // src | (rel<<17), sorted by dst

__device__ __forceinline__ uint32_t f2tf(float f) {
    uint32_t r;
    asm("cvt.rna.tf32.f32 %0, %1;" : "=r"(r) : "f"(f));
    return r;
}
__device__ __forceinline__ float f2tf_f(float f) { return __uint_as_float(f2tf(f)); }

__global__ void detect_kernel(const int* __restrict__ ei_raw) {
    if (threadIdx.x == 0 && blockIdx.x == 0) {
        int is64 = 1;
        for (int i = 0; i < 1024; i++)
            if (ei_raw[2 * i + 1] != 0) { is64 = 0; break; }
        g_is64 = is64;
    }
}

__device__ __forceinline__ int edge_at(const void* __restrict__ p, size_t i) {
    if (g_is64) return (int)((const long long*)p)[i];
    return ((const int*)p)[i];
}

// -------- prep: pack weights (tf32-rounded), fold classifier --------
__global__ void prep_kernel(const float* __restrict__ W1, const float* __restrict__ root1,
                            const float* __restrict__ W2, const float* __restrict__ root2,
                            const float* __restrict__ b2, const float* __restrict__ lin_w,
                            const float* __restrict__ lin_b) {
    int t = blockIdx.x * blockDim.x + threadIdx.x;
    int stride = gridDim.x * blockDim.x;
    for (int i = t; i < IND * NCOL; i += stride) {
        int k = i / NCOL, j = i % NCOL;
        float v;
        if (j < 256) v = W1[(j >> 5) * (IND * HID) + k * HID + (j & 31)];
        else         v = root1[k * HID + (j - 256)];
        g_wcat[i] = f2tf_f(v);
    }
    if (t < 512) {
        int idx = t >> 1, c = t & 1;
        const float* wrow = W2 + idx * OUTD;
        float s = 0.f;
        for (int o = 0; o < OUTD; o++) s += wrow[o] * lin_w[o * 2 + c];
        g_W2p[t] = s;
    }
    if (t < 64) {
        int k = t >> 1, c = t & 1;
        float s = 0.f;
        for (int o = 0; o < OUTD; o++) s += root2[k * OUTD + o] * lin_w[o * 2 + c];
        g_r2p[t] = s;
    }
    if (t < 2) {
        float s = lin_b[t];
        for (int o = 0; o < OUTD; o++) s += b2[o] * lin_w[o * 2 + t];
        g_bp[t] = s;
    }
}

// -------- fused: zero histogram + pre-round x to tf32 --------
__global__ void roundzero_kernel(const float* __restrict__ x) {
    int t = blockIdx.x * blockDim.x + threadIdx.x;
    int stride = gridDim.x * blockDim.x;
    for (int i = t; i < NN; i += stride) g_cnt[i] = 0;
    for (int i = t; i < NN * (IND / 4); i += stride) {
        float4 v = ((const float4*)x)[i];
        v.x = f2tf_f(v.x); v.y = f2tf_f(v.y); v.z = f2tf_f(v.z); v.w = f2tf_f(v.w);
        ((float4*)g_xr)[i] = v;
    }
}

// -------- counting sort by dst --------
__global__ __launch_bounds__(256) void hist_kernel(const void* __restrict__ ei) {
    int e = blockIdx.x * 256 + threadIdx.x;   // NE threads exactly
    int dst = edge_at(ei, (size_t)NE + e);
    atomicAdd(&g_cnt[dst], 1);
}

__global__ __launch_bounds__(256) void scan1_kernel() {
    __shared__ int wtot[8];
    int b = blockIdx.x, t = threadIdx.x;
    int lane = t & 31, w = t >> 5;
    int base = b * 1024 + t * 4;
    int v0 = (base + 0 < NN) ? g_cnt[base + 0] : 0;
    int v1 = (base + 1 < NN) ? g_cnt[base + 1] : 0;
    int v2 = (base + 2 < NN) ? g_cnt[base + 2] : 0;
    int v3 = (base + 3 < NN) ? g_cnt[base + 3] : 0;
    int mysum = v0 + v1 + v2 + v3;
    int s = mysum;
#pragma unroll
    for (int o = 1; o < 32; o <<= 1) {
        int y = __shfl_up_sync(0xFFFFFFFFu, s, o);
        if (lane >= o) s += y;
    }
    if (lane == 31) wtot[w] = s;
    __syncthreads();
    if (t < 8) {
        int x = wtot[t];
#pragma unroll
        for (int o = 1; o < 8; o <<= 1) {
            int y = __shfl_up_sync(0xFFu, x, o);
            if (t >= o) x += y;
        }
        wtot[t] = x;
    }
    __syncthreads();
    int wbase = w ? wtot[w - 1] : 0;
    int excl = wbase + s - mysum;
    if (base + 0 < NN) g_off[base + 0] = excl;
    if (base + 1 < NN) g_off[base + 1] = excl + v0;
    if (base + 2 < NN) g_off[base + 2] = excl + v0 + v1;
    if (base + 3 < NN) g_off[base + 3] = excl + v0 + v1 + v2;
    if (t == 0) g_bsum[b] = wtot[7];
}

__global__ void scan2_kernel() {
    __shared__ int sm[128];
    int t = threadIdx.x;
    int v = (t < NB_SCAN) ? g_bsum[t] : 0;
    sm[t] = v;
    __syncthreads();
    for (int o = 1; o < 128; o <<= 1) {
        int y = (t >= o) ? sm[t - o] : 0;
        __syncthreads();
        sm[t] += y;
        __syncthreads();
    }
    g_boff[t] = sm[t] - v;   // exclusive
}

__global__ __launch_bounds__(256) void scan3_kernel() {
    int b = blockIdx.x, t = threadIdx.x;
    int base = b * 1024 + t * 4;
    int add = g_boff[b];
#pragma unroll
    for (int k = 0; k < 4; k++) {
        int i = base + k;
        if (i < NN) {
            int o = g_off[i] + add;
            g_off[i] = o;
            g_pos[i] = o;
            g_deg[i] = (float)g_cnt[i];
        }
    }
    if (b == 0 && t == 0) g_off[NN] = NE;
}

__global__ __launch_bounds__(256) void place_kernel(const void* __restrict__ ei,
                                                    const void* __restrict__ et) {
    int e = blockIdx.x * 256 + threadIdx.x;   // NE threads exactly
    int src = edge_at(ei, e);
    int dst = edge_at(ei, (size_t)NE + e);
    int r   = edge_at(et, e);
    int p = atomicAdd(&g_pos[dst], 1);
    g_epack[p] = src | (r << 17);
}

// -------- tf32 tensor-core GEMM (cp.async double-buffered) --------
#define GBM 128
#define GBN 96
#define GBK 32
#define A_STRIDE 36
#define B_STRIDE 100
#define GEMM_SMEM ((2 * GBM * A_STRIDE + 2 * GBK * B_STRIDE) * 4)

__device__ __forceinline__ void cpa16(uint32_t dst_s, const void* src, int sz) {
    asm volatile("cp.async.ca.shared.global [%0], [%1], 16, %2;\n"
                 :: "r"(dst_s), "l"(src), "r"(sz));
}

__global__ __launch_bounds__(256) void gemm_tf32_kernel() {
    extern __shared__ uint32_t smem[];
    uint32_t* As = smem;
    uint32_t* Bs = smem + 2 * GBM * A_STRIDE;
    uint32_t smem_base = (uint32_t)__cvta_generic_to_shared(smem);
    uint32_t bs_base = smem_base + 2 * GBM * A_STRIDE * 4;

    int tid  = threadIdx.x;
    int lane = tid & 31, wid = tid >> 5;
    int warp_m = wid & 3, warp_n = wid >> 2;
    int br = blockIdx.x * GBM;
    int bc = blockIdx.y * GBN;
    int gID = lane >> 2, tig = lane & 3;

    float c[2][6][4];
#pragma unroll
    for (int mt = 0; mt < 2; mt++)
#pragma unroll
        for (int nt = 0; nt < 6; nt++)
#pragma unroll
            for (int q = 0; q < 4; q++) c[mt][nt][q] = 0.f;

    auto load_stage = [&](int s, int k0) {
        uint32_t a_base = smem_base + (uint32_t)s * GBM * A_STRIDE * 4;
        uint32_t b_base = bs_base + (uint32_t)s * GBK * B_STRIDE * 4;
#pragma unroll
        for (int j = 0; j < 4; j++) {
            int cch = tid + j * 256;
            int row = cch >> 3, kc = cch & 7;
            int gr = br + row;
            const float* src = g_xr + (size_t)(gr < NN ? gr : 0) * IND + k0 + kc * 4;
            cpa16(a_base + (row * A_STRIDE + kc * 4) * 4, src, gr < NN ? 16 : 0);
        }
#pragma unroll
        for (int j = 0; j < 3; j++) {
            int cch = tid + j * 256;
            int row = cch / 24, seg = cch % 24;
            const float* src = g_wcat + (k0 + row) * NCOL + bc + seg * 4;
            cpa16(b_base + (row * B_STRIDE + seg * 4) * 4, src, 16);
        }
    };

    load_stage(0, 0);
    asm volatile("cp.async.commit_group;\n");

#pragma unroll
    for (int it = 0; it < 4; it++) {
        if (it < 3) {
            load_stage((it + 1) & 1, (it + 1) * GBK);
            asm volatile("cp.async.commit_group;\n");
            asm volatile("cp.async.wait_group 1;\n");
        } else {
            asm volatile("cp.async.wait_group 0;\n");
        }
        __syncthreads();

        const uint32_t* Ac = As + (it & 1) * GBM * A_STRIDE;
        const uint32_t* Bc = Bs + (it & 1) * GBK * B_STRIDE;
#pragma unroll
        for (int ks = 0; ks < 4; ks++) {
            int kb = ks * 8;
            uint32_t a[2][4];
#pragma unroll
            for (int mt = 0; mt < 2; mt++) {
                int r0 = warp_m * 32 + mt * 16 + gID;
                a[mt][0] = Ac[r0 * A_STRIDE + kb + tig];
                a[mt][1] = Ac[(r0 + 8) * A_STRIDE + kb + tig];
                a[mt][2] = Ac[r0 * A_STRIDE + kb + tig + 4];
                a[mt][3] = Ac[(r0 + 8) * A_STRIDE + kb + tig + 4];
            }
            uint32_t b[6][2];
#pragma unroll
            for (int nt = 0; nt < 6; nt++) {
                int col = warp_n * 48 + nt * 8 + gID;
                b[nt][0] = Bc[(kb + tig) * B_STRIDE + col];
                b[nt][1] = Bc[(kb + tig + 4) * B_STRIDE + col];
            }
#pragma unroll
            for (int mt = 0; mt < 2; mt++)
#pragma unroll
                for (int nt = 0; nt < 6; nt++)
                    asm volatile(
                        "mma.sync.aligned.m16n8k8.row.col.f32.tf32.tf32.f32 "
                        "{%0,%1,%2,%3}, {%4,%5,%6,%7}, {%8,%9}, {%0,%1,%2,%3};"
                        : "+f"(c[mt][nt][0]), "+f"(c[mt][nt][1]),
                          "+f"(c[mt][nt][2]), "+f"(c[mt][nt][3])
                        : "r"(a[mt][0]), "r"(a[mt][1]), "r"(a[mt][2]), "r"(a[mt][3]),
                          "r"(b[nt][0]), "r"(b[nt][1]));
        }
        __syncthreads();
    }

#pragma unroll
    for (int mt = 0; mt < 2; mt++) {
        int row0 = br + warp_m * 32 + mt * 16 + gID;
#pragma unroll
        for (int nt = 0; nt < 6; nt++) {
            int col = bc + warp_n * 48 + nt * 8 + 2 * tig;
            if (row0 < NN)
                *(float2*)&g_y1[(size_t)row0 * NCOL + col] =
                    make_float2(c[mt][nt][0], c[mt][nt][1]);
            if (row0 + 8 < NN)
                *(float2*)&g_y1[(size_t)(row0 + 8) * NCOL + col] =
                    make_float2(c[mt][nt][2], c[mt][nt][3]);
        }
    }
}

// -------- layer-1 pull aggregation: warp per dst, no atomics --------
__global__ __launch_bounds__(256) void agg1_pull_kernel() {
    int n = (blockIdx.x * 256 + threadIdx.x) >> 5;
    if (n >= NN) return;
    int lane = threadIdx.x & 31;
    int c = lane & 7, sub = lane >> 3;
    int lo = g_off[n], hi = g_off[n + 1];
    float4 acc = make_float4(0.f, 0.f, 0.f, 0.f);
    for (int j = lo + sub; j < hi; j += 4) {
        int p = g_epack[j];
        int s = p & 0x1FFFF, r = p >> 17;
        float4 v = *(const float4*)&g_y1[(size_t)s * NCOL + r * HID + c * 4];
        acc.x += v.x; acc.y += v.y; acc.z += v.z; acc.w += v.w;
    }
#pragma unroll
    for (int o = 8; o <= 16; o <<= 1) {
        acc.x += __shfl_xor_sync(0xFFFFFFFFu, acc.x, o);
        acc.y += __shfl_xor_sync(0xFFFFFFFFu, acc.y, o);
        acc.z += __shfl_xor_sync(0xFFFFFFFFu, acc.z, o);
        acc.w += __shfl_xor_sync(0xFFFFFFFFu, acc.w, o);
    }
    if (sub == 0)
        *(float4*)&g_agg1[n * HID + c * 4] = acc;
}

// -------- h = relu(agg1/deg + x@root1 + b1);  y2[n,r,:] = h[n] @ W2p[r] --------
__global__ __launch_bounds__(256) void h_y2_kernel(const float* __restrict__ b1) {
    __shared__ float sh[32][33];
    __shared__ float sw[512];
    int t = threadIdx.x;
    int n0 = blockIdx.x * 32;
    sw[t] = g_W2p[t];
    sw[t + 256] = g_W2p[t + 256];
#pragma unroll
    for (int j = 0; j < 4; j++) {
        int i = t + j * 256;
        int n_l = i >> 5, k = i & 31;
        int n = n0 + n_l;
        int gi = n * 32 + k;
        float d = g_deg[n];
        d = d > 1.f ? d : 1.f;
        float v = g_agg1[gi] / d + g_y1[(size_t)n * NCOL + 256 + k] + b1[k];
        v = v > 0.f ? v : 0.f;
        g_h[gi] = v;
        sh[n_l][k] = v;
    }
    __syncthreads();
    int n_l = t >> 3, r = t & 7;
    float c0 = 0.f, c1 = 0.f;
#pragma unroll
    for (int k = 0; k < 32; k++) {
        float hv = sh[n_l][k];
        float2 w = *(const float2*)&sw[(r * 32 + k) * 2];
        c0 += hv * w.x;
        c1 += hv * w.y;
    }
    *(float2*)&g_y2[(n0 + n_l) * 16 + r * 2] = make_float2(c0, c1);
}

// -------- fused layer-2 pull + output: warp per dst, no atomics --------
__global__ __launch_bounds__(256) void aggout_kernel(float* __restrict__ out) {
    int n = (blockIdx.x * 256 + threadIdx.x) >> 5;
    if (n >= NN) return;
    int lane = threadIdx.x & 31;
    int lo = g_off[n], hi = g_off[n + 1];
    float m0 = 0.f, m1 = 0.f;
    for (int j = lo + lane; j < hi; j += 32) {
        int p = g_epack[j];
        int s = p & 0x1FFFF, r = p >> 17;
        float2 v = *(const float2*)&g_y2[s * 16 + r * 2];
        m0 += v.x; m1 += v.y;
    }
    float deg = (float)(hi - lo);
    float inv = 1.f / fmaxf(deg, 1.f);
    float hv = g_h[n * HID + lane];
    float t0 = m0 * inv + hv * g_r2p[lane * 2 + 0];
    float t1 = m1 * inv + hv * g_r2p[lane * 2 + 1];
#pragma unroll
    for (int o = 16; o; o >>= 1) {
        t0 += __shfl_xor_sync(0xFFFFFFFFu, t0, o);
        t1 += __shfl_xor_sync(0xFFFFFFFFu, t1, o);
    }
    if (lane == 0) {
        out[n * 2 + 0] = t0 + g_bp[0];
        out[n * 2 + 1] = t1 + g_bp[1];
    }
}

extern "C" void kernel_launch(void* const* d_in, const int* in_sizes, int n_in,
                              void* d_out, int out_size) {
    const float* x     = (const float*)d_in[0];
    const void*  ei    = d_in[1];
    const void*  et    = d_in[2];
    const float* W1    = (const float*)d_in[3];
    const float* root1 = (const float*)d_in[4];
    const float* b1    = (const float*)d_in[5];
    const float* W2    = (const float*)d_in[6];
    const float* root2 = (const float*)d_in[7];
    const float* b2    = (const float*)d_in[8];
    const float* lin_w = (const float*)d_in[9];
    const float* lin_b = (const float*)d_in[10];
    float* out         = (float*)d_out;

    cudaFuncSetAttribute(gemm_tf32_kernel,
                         cudaFuncAttributeMaxDynamicSharedMemorySize, GEMM_SMEM);

    detect_kernel<<<1, 32>>>((const int*)ei);
    prep_kernel<<<145, 256>>>(W1, root1, W2, root2, b2, lin_w, lin_b);
    roundzero_kernel<<<4096, 256>>>(x);
    hist_kernel<<<NE / 256, 256>>>(ei);
    scan1_kernel<<<NB_SCAN, 256>>>();
    scan2_kernel<<<1, 128>>>();
    scan3_kernel<<<NB_SCAN, 256>>>();
    place_kernel<<<NE / 256, 256>>>(ei, et);
    gemm_tf32_kernel<<<dim3((NN + GBM - 1) / GBM, NCOL / GBN), 256, GEMM_SMEM>>>();
    agg1_pull_kernel<<<(NN * 32 + 255) / 256, 256>>>();
    h_y2_kernel<<<NN / 32, 256>>>(b1);
    aggout_kernel<<<(NN * 32 + 255) / 256, 256>>>(out);
}

// round 8
// speedup vs baseline: 1.6029x; 1.6029x over previous
#include <cuda_runtime.h>
#include <cuda_bf16.h>
#include <cstdint>

#define NN 100000
#define NE 1600000
#define IND 128
#define HID 32
#define OUTD 64
#define NCOL 288   // 8*32 + 32 (root)

#define QSCALE 16384.0f          // 2^14
#define QINV   (1.0f / 16384.0f)
#define QBIAS  (1u << 24)

// -------- scratch (static device memory; 16B-aligned) --------
__device__ __align__(16) float g_wcat[IND * NCOL];            // tf32-rounded [k][j]
__device__ __align__(16) float g_y1[(size_t)NN * NCOL];       // x @ [W1 | root1]  (115 MB)
__device__ __align__(16) unsigned long long g_agg1q[NN * 16]; // packed fixed-point agg (12.8 MB)
__device__ __align__(16) unsigned long long g_acc2q[NN];      // packed fixed-point layer-2 acc
__device__ __align__(16) float g_deg[NN];
__device__ __align__(16) float g_h[NN * HID];
__device__ __align__(16) float g_y2[NN * 16];                 // [n][r][c]: h @ W2p
__device__ __align__(16) float g_W2p[512];
__device__ __align__(16) float g_r2p[64];
__device__ __align__(16) float g_bp[2];
__device__ int g_is64;

__device__ __forceinline__ uint32_t f2tf(float f) {
    uint32_t r;
    asm("cvt.rna.tf32.f32 %0, %1;" : "=r"(r) : "f"(f));
    return r;
}
__device__ __forceinline__ float f2tf_f(float f) { return __uint_as_float(f2tf(f)); }

__global__ void detect_kernel(const int* __restrict__ ei_raw) {
    if (threadIdx.x == 0 && blockIdx.x == 0) {
        int is64 = 1;
        for (int i = 0; i < 1024; i++)
            if (ei_raw[2 * i + 1] != 0) { is64 = 0; break; }
        g_is64 = is64;
    }
}

__device__ __forceinline__ int edge_at(const void* __restrict__ p, size_t i) {
    if (g_is64) return (int)((const long long*)p)[i];
    return ((const int*)p)[i];
}

// -------- prep: pack weights (tf32-rounded), fold classifier --------
__global__ void prep_kernel(const float* __restrict__ W1, const float* __restrict__ root1,
                            const float* __restrict__ W2, const float* __restrict__ root2,
                            const float* __restrict__ b2, const float* __restrict__ lin_w,
                            const float* __restrict__ lin_b) {
    int t = blockIdx.x * blockDim.x + threadIdx.x;
    int stride = gridDim.x * blockDim.x;
    for (int i = t; i < IND * NCOL; i += stride) {
        int k = i / NCOL, j = i % NCOL;
        float v;
        if (j < 256) v = W1[(j >> 5) * (IND * HID) + k * HID + (j & 31)];
        else         v = root1[k * HID + (j - 256)];
        g_wcat[i] = f2tf_f(v);
    }
    if (t < 512) {
        int idx = t >> 1, c = t & 1;
        const float* wrow = W2 + idx * OUTD;
        float s = 0.f;
        for (int o = 0; o < OUTD; o++) s += wrow[o] * lin_w[o * 2 + c];
        g_W2p[t] = s;
    }
    if (t < 64) {
        int k = t >> 1, c = t & 1;
        float s = 0.f;
        for (int o = 0; o < OUTD; o++) s += root2[k * OUTD + o] * lin_w[o * 2 + c];
        g_r2p[t] = s;
    }
    if (t < 2) {
        float s = lin_b[t];
        for (int o = 0; o < OUTD; o++) s += b2[o] * lin_w[o * 2 + t];
        g_bp[t] = s;
    }
}

// -------- zero accumulators --------
__global__ void zero_kernel() {
    int t = blockIdx.x * blockDim.x + threadIdx.x;
    int stride = gridDim.x * blockDim.x;
    float4 z = make_float4(0.f, 0.f, 0.f, 0.f);
    for (int i = t; i < NN * 8; i += stride) ((float4*)g_agg1q)[i] = z;
    for (int i = t; i < NN / 2; i += stride) ((float4*)g_acc2q)[i] = z;
    for (int i = t; i < NN / 4; i += stride) ((float4*)g_deg)[i]   = z;
}

// -------- tf32 tensor-core GEMM (cp.async double-buffered, A converted post-LDS) --------
#define GBM 128
#define GBN 96
#define GBK 32
#define A_STRIDE 36
#define B_STRIDE 100
#define GEMM_SMEM ((2 * GBM * A_STRIDE + 2 * GBK * B_STRIDE) * 4)

__device__ __forceinline__ void cpa16(uint32_t dst_s, const void* src, int sz) {
    asm volatile("cp.async.ca.shared.global [%0], [%1], 16, %2;\n"
                 :: "r"(dst_s), "l"(src), "r"(sz));
}

__global__ __launch_bounds__(256) void gemm_tf32_kernel(const float* __restrict__ x) {
    extern __shared__ uint32_t smem[];
    uint32_t* As = smem;
    uint32_t* Bs = smem + 2 * GBM * A_STRIDE;
    uint32_t smem_base = (uint32_t)__cvta_generic_to_shared(smem);
    uint32_t bs_base = smem_base + 2 * GBM * A_STRIDE * 4;

    int tid  = threadIdx.x;
    int lane = tid & 31, wid = tid >> 5;
    int warp_m = wid & 3, warp_n = wid >> 2;
    int br = blockIdx.x * GBM;
    int bc = blockIdx.y * GBN;
    int gID = lane >> 2, tig = lane & 3;

    float c[2][6][4];
#pragma unroll
    for (int mt = 0; mt < 2; mt++)
#pragma unroll
        for (int nt = 0; nt < 6; nt++)
#pragma unroll
            for (int q = 0; q < 4; q++) c[mt][nt][q] = 0.f;

    auto load_stage = [&](int s, int k0) {
        uint32_t a_base = smem_base + (uint32_t)s * GBM * A_STRIDE * 4;
        uint32_t b_base = bs_base + (uint32_t)s * GBK * B_STRIDE * 4;
#pragma unroll
        for (int j = 0; j < 4; j++) {
            int cch = tid + j * 256;
            int row = cch >> 3, kc = cch & 7;
            int gr = br + row;
            const float* src = x + (size_t)(gr < NN ? gr : 0) * IND + k0 + kc * 4;
            cpa16(a_base + (row * A_STRIDE + kc * 4) * 4, src, gr < NN ? 16 : 0);
        }
#pragma unroll
        for (int j = 0; j < 3; j++) {
            int cch = tid + j * 256;
            int row = cch / 24, seg = cch % 24;
            const float* src = g_wcat + (k0 + row) * NCOL + bc + seg * 4;
            cpa16(b_base + (row * B_STRIDE + seg * 4) * 4, src, 16);
        }
    };

    load_stage(0, 0);
    asm volatile("cp.async.commit_group;\n");

#pragma unroll
    for (int it = 0; it < 4; it++) {
        if (it < 3) {
            load_stage((it + 1) & 1, (it + 1) * GBK);
            asm volatile("cp.async.commit_group;\n");
            asm volatile("cp.async.wait_group 1;\n");
        } else {
            asm volatile("cp.async.wait_group 0;\n");
        }
        __syncthreads();

        const uint32_t* Ac = As + (it & 1) * GBM * A_STRIDE;
        const uint32_t* Bc = Bs + (it & 1) * GBK * B_STRIDE;
#pragma unroll
        for (int ks = 0; ks < 4; ks++) {
            int kb = ks * 8;
            uint32_t a[2][4];
#pragma unroll
            for (int mt = 0; mt < 2; mt++) {
                int r0 = warp_m * 32 + mt * 16 + gID;
                a[mt][0] = f2tf(__uint_as_float(Ac[r0 * A_STRIDE + kb + tig]));
                a[mt][1] = f2tf(__uint_as_float(Ac[(r0 + 8) * A_STRIDE + kb + tig]));
                a[mt][2] = f2tf(__uint_as_float(Ac[r0 * A_STRIDE + kb + tig + 4]));
                a[mt][3] = f2tf(__uint_as_float(Ac[(r0 + 8) * A_STRIDE + kb + tig + 4]));
            }
            uint32_t b[6][2];
#pragma unroll
            for (int nt = 0; nt < 6; nt++) {
                int col = warp_n * 48 + nt * 8 + gID;
                b[nt][0] = Bc[(kb + tig) * B_STRIDE + col];
                b[nt][1] = Bc[(kb + tig + 4) * B_STRIDE + col];
            }
#pragma unroll
            for (int mt = 0; mt < 2; mt++)
#pragma unroll
                for (int nt = 0; nt < 6; nt++)
                    asm volatile(
                        "mma.sync.aligned.m16n8k8.row.col.f32.tf32.tf32.f32 "
                        "{%0,%1,%2,%3}, {%4,%5,%6,%7}, {%8,%9}, {%0,%1,%2,%3};"
                        : "+f"(c[mt][nt][0]), "+f"(c[mt][nt][1]),
                          "+f"(c[mt][nt][2]), "+f"(c[mt][nt][3])
                        : "r"(a[mt][0]), "r"(a[mt][1]), "r"(a[mt][2]), "r"(a[mt][3]),
                          "r"(b[nt][0]), "r"(b[nt][1]));
        }
        __syncthreads();
    }

#pragma unroll
    for (int mt = 0; mt < 2; mt++) {
        int row0 = br + warp_m * 32 + mt * 16 + gID;
#pragma unroll
        for (int nt = 0; nt < 6; nt++) {
            int col = bc + warp_n * 48 + nt * 8 + 2 * tig;
            if (row0 < NN)
                *(float2*)&g_y1[(size_t)row0 * NCOL + col] =
                    make_float2(c[mt][nt][0], c[mt][nt][1]);
            if (row0 + 8 < NN)
                *(float2*)&g_y1[(size_t)(row0 + 8) * NCOL + col] =
                    make_float2(c[mt][nt][2], c[mt][nt][3]);
        }
    }
}

// -------- layer-1 scatter: packed fixed-point u64 atomics --------
__global__ __launch_bounds__(256) void scatter1_kernel(const void* __restrict__ ei,
                                                       const void* __restrict__ et) {
    int t = blockIdx.x * blockDim.x + threadIdx.x;   // NE*8 threads exactly
    int e = t >> 3, c = t & 7;
    int src = edge_at(ei, e);
    int dst = edge_at(ei, (size_t)NE + e);
    int r   = edge_at(et, e);
    float4 v = *(const float4*)&g_y1[(size_t)src * NCOL + r * HID + c * 4];
    unsigned q0 = (unsigned)__float2int_rn(v.x * QSCALE) + QBIAS;
    unsigned q1 = (unsigned)__float2int_rn(v.y * QSCALE) + QBIAS;
    unsigned q2 = (unsigned)__float2int_rn(v.z * QSCALE) + QBIAS;
    unsigned q3 = (unsigned)__float2int_rn(v.w * QSCALE) + QBIAS;
    unsigned long long p0 = (unsigned long long)q0 | ((unsigned long long)q1 << 32);
    unsigned long long p1 = (unsigned long long)q2 | ((unsigned long long)q3 << 32);
    atomicAdd(&g_agg1q[(dst * 8 + c) * 2 + 0], p0);
    atomicAdd(&g_agg1q[(dst * 8 + c) * 2 + 1], p1);
    if (c == 0) atomicAdd(&g_deg[dst], 1.0f);
}

// -------- h = relu(agg1/deg + x@root1 + b1);  y2[n,r,:] = h[n] @ W2p[r] --------
__global__ __launch_bounds__(256) void h_y2_kernel(const float* __restrict__ b1) {
    __shared__ float sh[32][33];
    __shared__ float sw[512];
    int t = threadIdx.x;
    int n0 = blockIdx.x * 32;
    sw[t] = g_W2p[t];
    sw[t + 256] = g_W2p[t + 256];
    const unsigned* aggw = (const unsigned*)g_agg1q;
#pragma unroll
    for (int j = 0; j < 4; j++) {
        int i = t + j * 256;
        int n_l = i >> 5, k = i & 31;
        int n = n0 + n_l;
        float d = g_deg[n];
        unsigned di = (unsigned)(int)d;
        unsigned u = aggw[n * 32 + k];
        float agg = (float)(int)(u - di * QBIAS) * QINV;
        d = d > 1.f ? d : 1.f;
        float v = agg / d + g_y1[(size_t)n * NCOL + 256 + k] + b1[k];
        v = v > 0.f ? v : 0.f;
        g_h[n * 32 + k] = v;
        sh[n_l][k] = v;
    }
    __syncthreads();
    int n_l = t >> 3, r = t & 7;
    float c0 = 0.f, c1 = 0.f;
#pragma unroll
    for (int k = 0; k < 32; k++) {
        float hv = sh[n_l][k];
        float2 w = *(const float2*)&sw[(r * 32 + k) * 2];
        c0 += hv * w.x;
        c1 += hv * w.y;
    }
    *(float2*)&g_y2[(n0 + n_l) * 16 + r * 2] = make_float2(c0, c1);
}

// -------- layer-2 scatter: one packed u64 atomic per edge --------
__global__ __launch_bounds__(256) void scatter2_kernel(const void* __restrict__ ei,
                                                       const void* __restrict__ et) {
    int e = blockIdx.x * blockDim.x + threadIdx.x;   // NE threads exactly
    int src = edge_at(ei, e);
    int dst = edge_at(ei, (size_t)NE + e);
    int r   = edge_at(et, e);
    float2 v = *(const float2*)&g_y2[src * 16 + r * 2];
    unsigned q0 = (unsigned)__float2int_rn(v.x * QSCALE) + QBIAS;
    unsigned q1 = (unsigned)__float2int_rn(v.y * QSCALE) + QBIAS;
    atomicAdd(&g_acc2q[dst], (unsigned long long)q0 | ((unsigned long long)q1 << 32));
}

// -------- out[n] = acc2[n]/deg + h[n] @ r2p + bp --------
__global__ __launch_bounds__(256) void out2_kernel(float* __restrict__ out) {
    int n = blockIdx.x * 256 + threadIdx.x;
    if (n >= NN) return;
    float d = g_deg[n];
    unsigned di = (unsigned)(int)d;
    unsigned long long p = g_acc2q[n];
    float m0 = (float)(int)((unsigned)p - di * QBIAS) * QINV;
    float m1 = (float)(int)((unsigned)(p >> 32) - di * QBIAS) * QINV;
    d = d > 1.f ? d : 1.f;
    float inv = 1.f / d;
    float c0 = m0 * inv;
    float c1 = m1 * inv;
#pragma unroll
    for (int k = 0; k < 32; k++) {
        float hv = g_h[n * 32 + k];
        c0 += hv * g_r2p[k * 2 + 0];
        c1 += hv * g_r2p[k * 2 + 1];
    }
    out[n * 2 + 0] = c0 + g_bp[0];
    out[n * 2 + 1] = c1 + g_bp[1];
}

extern "C" void kernel_launch(void* const* d_in, const int* in_sizes, int n_in,
                              void* d_out, int out_size) {
    const float* x     = (const float*)d_in[0];
    const void*  ei    = d_in[1];
    const void*  et    = d_in[2];
    const float* W1    = (const float*)d_in[3];
    const float* root1 = (const float*)d_in[4];
    const float* b1    = (const float*)d_in[5];
    const float* W2    = (const float*)d_in[6];
    const float* root2 = (const float*)d_in[7];
    const float* b2    = (const float*)d_in[8];
    const float* lin_w = (const float*)d_in[9];
    const float* lin_b = (const float*)d_in[10];
    float* out         = (float*)d_out;

    cudaFuncSetAttribute(gemm_tf32_kernel,
                         cudaFuncAttributeMaxDynamicSharedMemorySize, GEMM_SMEM);

    detect_kernel<<<1, 32>>>((const int*)ei);
    prep_kernel<<<145, 256>>>(W1, root1, W2, root2, b2, lin_w, lin_b);
    zero_kernel<<<2048, 256>>>();
    gemm_tf32_kernel<<<dim3((NN + GBM - 1) / GBM, NCOL / GBN), 256, GEMM_SMEM>>>(x);
    scatter1_kernel<<<(NE * 8) / 256, 256>>>(ei, et);
    h_y2_kernel<<<NN / 32, 256>>>(b1);
    scatter2_kernel<<<NE / 256, 256>>>(ei, et);
    out2_kernel<<<(NN + 255) / 256, 256>>>(out);
}

// round 9
// speedup vs baseline: 1.8354x; 1.1450x over previous
#include <cuda_runtime.h>
#include <cuda_fp16.h>
#include <cstdint>

#define NN 100000
#define NE 1600000
#define IND 128
#define HID 32
#define OUTD 64
#define NCOL 288   // 8*32 + 32 (root)

// layer-1 16-bit fixed point: lane = deg*1024 + round(v*128)
#define S1 128.0f
#define S1INV (1.0f / 128.0f)
#define B1Q 1024
// layer-2 32-bit fixed point: lane = deg*2^24 + round(v*16384)
#define QSCALE 16384.0f
#define QINV   (1.0f / 16384.0f)
#define QBIAS  (1u << 24)

// -------- scratch (static device memory; 16B-aligned) --------
__device__ __align__(16) float g_wcat[IND * NCOL];              // tf32-rounded [k][j]
__device__ __align__(16) __half g_y1h[(size_t)NN * NCOL];       // fp16 y1 (57 MB)
__device__ __align__(16) unsigned long long g_agg1q[NN * 8];    // 16-bit×4 lanes per u64 (6.4 MB)
__device__ __align__(16) unsigned long long g_acc2q[NN];        // 32-bit×2 lanes
__device__ __align__(16) int g_degi[NN];
__device__ __align__(16) float g_h[NN * HID];
__device__ __align__(16) float g_y2[NN * 16];                   // [n][r][c]: h @ W2p
__device__ __align__(16) float g_W2p[512];
__device__ __align__(16) float g_r2p[64];
__device__ __align__(16) float g_bp[2];
__device__ int g_is64;

__device__ __forceinline__ uint32_t f2tf(float f) {
    uint32_t r;
    asm("cvt.rna.tf32.f32 %0, %1;" : "=r"(r) : "f"(f));
    return r;
}
__device__ __forceinline__ float f2tf_f(float f) { return __uint_as_float(f2tf(f)); }

__global__ void detect_kernel(const int* __restrict__ ei_raw) {
    if (threadIdx.x == 0 && blockIdx.x == 0) {
        int is64 = 1;
        for (int i = 0; i < 1024; i++)
            if (ei_raw[2 * i + 1] != 0) { is64 = 0; break; }
        g_is64 = is64;
    }
}

__device__ __forceinline__ int edge_at(const void* __restrict__ p, size_t i) {
    if (g_is64) return (int)((const long long*)p)[i];
    return ((const int*)p)[i];
}

// -------- prep: pack weights (tf32-rounded), fold classifier --------
__global__ void prep_kernel(const float* __restrict__ W1, const float* __restrict__ root1,
                            const float* __restrict__ W2, const float* __restrict__ root2,
                            const float* __restrict__ b2, const float* __restrict__ lin_w,
                            const float* __restrict__ lin_b) {
    int t = blockIdx.x * blockDim.x + threadIdx.x;
    int stride = gridDim.x * blockDim.x;
    for (int i = t; i < IND * NCOL; i += stride) {
        int k = i / NCOL, j = i % NCOL;
        float v;
        if (j < 256) v = W1[(j >> 5) * (IND * HID) + k * HID + (j & 31)];
        else         v = root1[k * HID + (j - 256)];
        g_wcat[i] = f2tf_f(v);
    }
    if (t < 512) {
        int idx = t >> 1, c = t & 1;
        const float* wrow = W2 + idx * OUTD;
        float s = 0.f;
        for (int o = 0; o < OUTD; o++) s += wrow[o] * lin_w[o * 2 + c];
        g_W2p[t] = s;
    }
    if (t < 64) {
        int k = t >> 1, c = t & 1;
        float s = 0.f;
        for (int o = 0; o < OUTD; o++) s += root2[k * OUTD + o] * lin_w[o * 2 + c];
        g_r2p[t] = s;
    }
    if (t < 2) {
        float s = lin_b[t];
        for (int o = 0; o < OUTD; o++) s += b2[o] * lin_w[o * 2 + t];
        g_bp[t] = s;
    }
}

// -------- zero accumulators --------
__global__ void zero_kernel() {
    int t = blockIdx.x * blockDim.x + threadIdx.x;
    int stride = gridDim.x * blockDim.x;
    float4 z = make_float4(0.f, 0.f, 0.f, 0.f);
    for (int i = t; i < NN * 4; i += stride) ((float4*)g_agg1q)[i] = z;
    for (int i = t; i < NN / 2; i += stride) ((float4*)g_acc2q)[i] = z;
    for (int i = t; i < NN / 4; i += stride) ((float4*)g_degi)[i]  = z;
}

// -------- tf32 tensor-core GEMM (cp.async double-buffered, fp16 output) --------
#define GBM 128
#define GBN 96
#define GBK 32
#define A_STRIDE 36
#define B_STRIDE 100
#define GEMM_SMEM ((2 * GBM * A_STRIDE + 2 * GBK * B_STRIDE) * 4)

__device__ __forceinline__ void cpa16(uint32_t dst_s, const void* src, int sz) {
    asm volatile("cp.async.ca.shared.global [%0], [%1], 16, %2;\n"
                 :: "r"(dst_s), "l"(src), "r"(sz));
}

__global__ __launch_bounds__(256) void gemm_tf32_kernel(const float* __restrict__ x) {
    extern __shared__ uint32_t smem[];
    uint32_t* As = smem;
    uint32_t* Bs = smem + 2 * GBM * A_STRIDE;
    uint32_t smem_base = (uint32_t)__cvta_generic_to_shared(smem);
    uint32_t bs_base = smem_base + 2 * GBM * A_STRIDE * 4;

    int tid  = threadIdx.x;
    int lane = tid & 31, wid = tid >> 5;
    int warp_m = wid & 3, warp_n = wid >> 2;
    int br = blockIdx.x * GBM;
    int bc = blockIdx.y * GBN;
    int gID = lane >> 2, tig = lane & 3;

    float c[2][6][4];
#pragma unroll
    for (int mt = 0; mt < 2; mt++)
#pragma unroll
        for (int nt = 0; nt < 6; nt++)
#pragma unroll
            for (int q = 0; q < 4; q++) c[mt][nt][q] = 0.f;

    auto load_stage = [&](int s, int k0) {
        uint32_t a_base = smem_base + (uint32_t)s * GBM * A_STRIDE * 4;
        uint32_t b_base = bs_base + (uint32_t)s * GBK * B_STRIDE * 4;
#pragma unroll
        for (int j = 0; j < 4; j++) {
            int cch = tid + j * 256;
            int row = cch >> 3, kc = cch & 7;
            int gr = br + row;
            const float* src = x + (size_t)(gr < NN ? gr : 0) * IND + k0 + kc * 4;
            cpa16(a_base + (row * A_STRIDE + kc * 4) * 4, src, gr < NN ? 16 : 0);
        }
#pragma unroll
        for (int j = 0; j < 3; j++) {
            int cch = tid + j * 256;
            int row = cch / 24, seg = cch % 24;
            const float* src = g_wcat + (k0 + row) * NCOL + bc + seg * 4;
            cpa16(b_base + (row * B_STRIDE + seg * 4) * 4, src, 16);
        }
    };

    load_stage(0, 0);
    asm volatile("cp.async.commit_group;\n");

#pragma unroll
    for (int it = 0; it < 4; it++) {
        if (it < 3) {
            load_stage((it + 1) & 1, (it + 1) * GBK);
            asm volatile("cp.async.commit_group;\n");
            asm volatile("cp.async.wait_group 1;\n");
        } else {
            asm volatile("cp.async.wait_group 0;\n");
        }
        __syncthreads();

        const uint32_t* Ac = As + (it & 1) * GBM * A_STRIDE;
        const uint32_t* Bc = Bs + (it & 1) * GBK * B_STRIDE;
#pragma unroll
        for (int ks = 0; ks < 4; ks++) {
            int kb = ks * 8;
            uint32_t a[2][4];
#pragma unroll
            for (int mt = 0; mt < 2; mt++) {
                int r0 = warp_m * 32 + mt * 16 + gID;
                a[mt][0] = f2tf(__uint_as_float(Ac[r0 * A_STRIDE + kb + tig]));
                a[mt][1] = f2tf(__uint_as_float(Ac[(r0 + 8) * A_STRIDE + kb + tig]));
                a[mt][2] = f2tf(__uint_as_float(Ac[r0 * A_STRIDE + kb + tig + 4]));
                a[mt][3] = f2tf(__uint_as_float(Ac[(r0 + 8) * A_STRIDE + kb + tig + 4]));
            }
            uint32_t b[6][2];
#pragma unroll
            for (int nt = 0; nt < 6; nt++) {
                int col = warp_n * 48 + nt * 8 + gID;
                b[nt][0] = Bc[(kb + tig) * B_STRIDE + col];
                b[nt][1] = Bc[(kb + tig + 4) * B_STRIDE + col];
            }
#pragma unroll
            for (int mt = 0; mt < 2; mt++)
#pragma unroll
                for (int nt = 0; nt < 6; nt++)
                    asm volatile(
                        "mma.sync.aligned.m16n8k8.row.col.f32.tf32.tf32.f32 "
                        "{%0,%1,%2,%3}, {%4,%5,%6,%7}, {%8,%9}, {%0,%1,%2,%3};"
                        : "+f"(c[mt][nt][0]), "+f"(c[mt][nt][1]),
                          "+f"(c[mt][nt][2]), "+f"(c[mt][nt][3])
                        : "r"(a[mt][0]), "r"(a[mt][1]), "r"(a[mt][2]), "r"(a[mt][3]),
                          "r"(b[nt][0]), "r"(b[nt][1]));
        }
        __syncthreads();
    }

    // epilogue: write y1 as fp16
#pragma unroll
    for (int mt = 0; mt < 2; mt++) {
        int row0 = br + warp_m * 32 + mt * 16 + gID;
#pragma unroll
        for (int nt = 0; nt < 6; nt++) {
            int col = bc + warp_n * 48 + nt * 8 + 2 * tig;
            if (row0 < NN)
                *(__half2*)&g_y1h[(size_t)row0 * NCOL + col] =
                    __floats2half2_rn(c[mt][nt][0], c[mt][nt][1]);
            if (row0 + 8 < NN)
                *(__half2*)&g_y1h[(size_t)(row0 + 8) * NCOL + col] =
                    __floats2half2_rn(c[mt][nt][2], c[mt][nt][3]);
        }
    }
}

// -------- layer-1 scatter: fp16 gather + 16-bit fixed-point u64 atomics --------
__global__ __launch_bounds__(256) void scatter1_kernel(const void* __restrict__ ei,
                                                       const void* __restrict__ et) {
    int t = blockIdx.x * blockDim.x + threadIdx.x;   // NE*8 threads exactly
    int e = t >> 3, c = t & 7;
    int src = edge_at(ei, e);
    int dst = edge_at(ei, (size_t)NE + e);
    int r   = edge_at(et, e);
    // 8 threads cover one 64B fp16 row chunk: 8B each (4 halfs)
    uint2 raw = *(const uint2*)&g_y1h[(size_t)src * NCOL + r * HID + c * 4];
    float2 f01 = __half22float2(*(__half2*)&raw.x);
    float2 f23 = __half22float2(*(__half2*)&raw.y);
    unsigned q0 = (unsigned)(B1Q + __float2int_rn(f01.x * S1));
    unsigned q1 = (unsigned)(B1Q + __float2int_rn(f01.y * S1));
    unsigned q2 = (unsigned)(B1Q + __float2int_rn(f23.x * S1));
    unsigned q3 = (unsigned)(B1Q + __float2int_rn(f23.y * S1));
    unsigned long long p = (unsigned long long)q0 | ((unsigned long long)q1 << 16)
                         | ((unsigned long long)q2 << 32) | ((unsigned long long)q3 << 48);
    atomicAdd(&g_agg1q[dst * 8 + c], p);
    if (c == 0) atomicAdd(&g_degi[dst], 1);
}

// -------- h = relu(agg1/deg + x@root1 + b1);  y2[n,r,:] = h[n] @ W2p[r] --------
__global__ __launch_bounds__(256) void h_y2_kernel(const float* __restrict__ b1) {
    __shared__ float sh[32][33];
    __shared__ float sw[512];
    int t = threadIdx.x;
    int n0 = blockIdx.x * 32;
    sw[t] = g_W2p[t];
    sw[t + 256] = g_W2p[t + 256];
    const unsigned short* aggw = (const unsigned short*)g_agg1q;
#pragma unroll
    for (int j = 0; j < 4; j++) {
        int i = t + j * 256;
        int n_l = i >> 5, k = i & 31;
        int n = n0 + n_l;
        int di = g_degi[n];
        int u = (int)aggw[n * 32 + k];
        float sum = (float)(u - di * B1Q) * S1INV;
        float d = di > 1 ? (float)di : 1.f;
        float v = sum / d + __half2float(g_y1h[(size_t)n * NCOL + 256 + k]) + b1[k];
        v = v > 0.f ? v : 0.f;
        g_h[n * 32 + k] = v;
        sh[n_l][k] = v;
    }
    __syncthreads();
    int n_l = t >> 3, r = t & 7;
    float c0 = 0.f, c1 = 0.f;
#pragma unroll
    for (int k = 0; k < 32; k++) {
        float hv = sh[n_l][k];
        float2 w = *(const float2*)&sw[(r * 32 + k) * 2];
        c0 += hv * w.x;
        c1 += hv * w.y;
    }
    *(float2*)&g_y2[(n0 + n_l) * 16 + r * 2] = make_float2(c0, c1);
}

// -------- layer-2 scatter: one packed u64 atomic per edge --------
__global__ __launch_bounds__(256) void scatter2_kernel(const void* __restrict__ ei,
                                                       const void* __restrict__ et) {
    int e = blockIdx.x * blockDim.x + threadIdx.x;   // NE threads exactly
    int src = edge_at(ei, e);
    int dst = edge_at(ei, (size_t)NE + e);
    int r   = edge_at(et, e);
    float2 v = *(const float2*)&g_y2[src * 16 + r * 2];
    unsigned q0 = (unsigned)__float2int_rn(v.x * QSCALE) + QBIAS;
    unsigned q1 = (unsigned)__float2int_rn(v.y * QSCALE) + QBIAS;
    atomicAdd(&g_acc2q[dst], (unsigned long long)q0 | ((unsigned long long)q1 << 32));
}

// -------- out[n] = acc2[n]/deg + h[n] @ r2p + bp --------
__global__ __launch_bounds__(256) void out2_kernel(float* __restrict__ out) {
    int n = blockIdx.x * 256 + threadIdx.x;
    if (n >= NN) return;
    int di = g_degi[n];
    unsigned long long p = g_acc2q[n];
    float m0 = (float)(int)((unsigned)p - (unsigned)di * QBIAS) * QINV;
    float m1 = (float)(int)((unsigned)(p >> 32) - (unsigned)di * QBIAS) * QINV;
    float d = di > 1 ? (float)di : 1.f;
    float inv = 1.f / d;
    float c0 = m0 * inv;
    float c1 = m1 * inv;
#pragma unroll
    for (int k = 0; k < 32; k++) {
        float hv = g_h[n * 32 + k];
        c0 += hv * g_r2p[k * 2 + 0];
        c1 += hv * g_r2p[k * 2 + 1];
    }
    out[n * 2 + 0] = c0 + g_bp[0];
    out[n * 2 + 1] = c1 + g_bp[1];
}

extern "C" void kernel_launch(void* const* d_in, const int* in_sizes, int n_in,
                              void* d_out, int out_size) {
    const float* x     = (const float*)d_in[0];
    const void*  ei    = d_in[1];
    const void*  et    = d_in[2];
    const float* W1    = (const float*)d_in[3];
    const float* root1 = (const float*)d_in[4];
    const float* b1    = (const float*)d_in[5];
    const float* W2    = (const float*)d_in[6];
    const float* root2 = (const float*)d_in[7];
    const float* b2    = (const float*)d_in[8];
    const float* lin_w = (const float*)d_in[9];
    const float* lin_b = (const float*)d_in[10];
    float* out         = (float*)d_out;

    cudaFuncSetAttribute(gemm_tf32_kernel,
                         cudaFuncAttributeMaxDynamicSharedMemorySize, GEMM_SMEM);

    detect_kernel<<<1, 32>>>((const int*)ei);
    prep_kernel<<<145, 256>>>(W1, root1, W2, root2, b2, lin_w, lin_b);
    zero_kernel<<<2048, 256>>>();
    gemm_tf32_kernel<<<dim3((NN + GBM - 1) / GBM, NCOL / GBN), 256, GEMM_SMEM>>>(x);
    scatter1_kernel<<<(NE * 8) / 256, 256>>>(ei, et);
    h_y2_kernel<<<NN / 32, 256>>>(b1);
    scatter2_kernel<<<NE / 256, 256>>>(ei, et);
    out2_kernel<<<(NN + 255) / 256, 256>>>(out);
}

// round 12
// speedup vs baseline: 2.0140x; 1.0973x over previous
#include <cuda_runtime.h>
#include <cuda_fp16.h>
#include <cstdint>

#define NN 100000
#define NE 1600000
#define IND 128
#define HID 32
#define OUTD 64
#define NCOL 288   // 8*32 + 32 (root)

// layer-2 32-bit fixed point: lane = deg*2^24 + round(v*16384)
#define QSCALE 16384.0f
#define QINV   (1.0f / 16384.0f)
#define QBIAS  (1u << 24)

// -------- scratch (static device memory; 16B-aligned) --------
__device__ __align__(16) float g_wcat[IND * NCOL];              // tf32-rounded [k][j]
__device__ __align__(16) __half g_y1h[(size_t)NN * NCOL];       // fp16 y1 (57 MB)
__device__ __align__(16) __half g_agg1h[NN * HID];              // fp16 accumulators (6.4 MB)
__device__ __align__(16) unsigned long long g_acc2q[NN];        // 32-bit×2 lanes
__device__ __align__(16) int g_degi[NN];
__device__ __align__(16) float g_h[NN * HID];
__device__ __align__(16) float g_y2[NN * 16];                   // [n][r][c]: h @ W2p
__device__ __align__(16) float g_W2p[512];
__device__ __align__(16) float g_r2p[64];
__device__ __align__(16) float g_bp[2];
__device__ int g_is64;

__device__ __forceinline__ uint32_t f2tf(float f) {
    uint32_t r;
    asm("cvt.rna.tf32.f32 %0, %1;" : "=r"(r) : "f"(f));
    return r;
}
__device__ __forceinline__ float f2tf_f(float f) { return __uint_as_float(f2tf(f)); }

__global__ void detect_kernel(const int* __restrict__ ei_raw) {
    if (threadIdx.x == 0 && blockIdx.x == 0) {
        int is64 = 1;
        for (int i = 0; i < 1024; i++)
            if (ei_raw[2 * i + 1] != 0) { is64 = 0; break; }
        g_is64 = is64;
    }
}

__device__ __forceinline__ int edge_at(const void* __restrict__ p, size_t i) {
    if (g_is64) return (int)((const long long*)p)[i];
    return ((const int*)p)[i];
}

// -------- prep: pack weights (tf32-rounded), fold classifier --------
__global__ void prep_kernel(const float* __restrict__ W1, const float* __restrict__ root1,
                            const float* __restrict__ W2, const float* __restrict__ root2,
                            const float* __restrict__ b2, const float* __restrict__ lin_w,
                            const float* __restrict__ lin_b) {
    int t = blockIdx.x * blockDim.x + threadIdx.x;
    int stride = gridDim.x * blockDim.x;
    for (int i = t; i < IND * NCOL; i += stride) {
        int k = i / NCOL, j = i % NCOL;
        float v;
        if (j < 256) v = W1[(j >> 5) * (IND * HID) + k * HID + (j & 31)];
        else         v = root1[k * HID + (j - 256)];
        g_wcat[i] = f2tf_f(v);
    }
    if (t < 512) {
        int idx = t >> 1, c = t & 1;
        const float* wrow = W2 + idx * OUTD;
        float s = 0.f;
        for (int o = 0; o < OUTD; o++) s += wrow[o] * lin_w[o * 2 + c];
        g_W2p[t] = s;
    }
    if (t < 64) {
        int k = t >> 1, c = t & 1;
        float s = 0.f;
        for (int o = 0; o < OUTD; o++) s += root2[k * OUTD + o] * lin_w[o * 2 + c];
        g_r2p[t] = s;
    }
    if (t < 2) {
        float s = lin_b[t];
        for (int o = 0; o < OUTD; o++) s += b2[o] * lin_w[o * 2 + t];
        g_bp[t] = s;
    }
}

// -------- zero accumulators --------
__global__ void zero_kernel() {
    int t = blockIdx.x * blockDim.x + threadIdx.x;
    int stride = gridDim.x * blockDim.x;
    float4 z = make_float4(0.f, 0.f, 0.f, 0.f);
    for (int i = t; i < NN * 4; i += stride)  ((float4*)g_agg1h)[i] = z;
    for (int i = t; i < NN / 2; i += stride)  ((float4*)g_acc2q)[i] = z;
    for (int i = t; i < NN / 4; i += stride)  ((float4*)g_degi)[i]  = z;
}

// -------- tf32 tensor-core GEMM (cp.async double-buffered, fp16 output) --------
#define GBM 128
#define GBN 96
#define GBK 32
#define A_STRIDE 36
#define B_STRIDE 100
#define GEMM_SMEM ((2 * GBM * A_STRIDE + 2 * GBK * B_STRIDE) * 4)

__device__ __forceinline__ void cpa16(uint32_t dst_s, const void* src, int sz) {
    asm volatile("cp.async.ca.shared.global [%0], [%1], 16, %2;\n"
                 :: "r"(dst_s), "l"(src), "r"(sz));
}

__global__ __launch_bounds__(256) void gemm_tf32_kernel(const float* __restrict__ x) {
    extern __shared__ uint32_t smem[];
    uint32_t* As = smem;
    uint32_t* Bs = smem + 2 * GBM * A_STRIDE;
    uint32_t smem_base = (uint32_t)__cvta_generic_to_shared(smem);
    uint32_t bs_base = smem_base + 2 * GBM * A_STRIDE * 4;

    int tid  = threadIdx.x;
    int lane = tid & 31, wid = tid >> 5;
    int warp_m = wid & 3, warp_n = wid >> 2;
    int br = blockIdx.x * GBM;
    int bc = blockIdx.y * GBN;
    int gID = lane >> 2, tig = lane & 3;

    float c[2][6][4];
#pragma unroll
    for (int mt = 0; mt < 2; mt++)
#pragma unroll
        for (int nt = 0; nt < 6; nt++)
#pragma unroll
            for (int q = 0; q < 4; q++) c[mt][nt][q] = 0.f;

    auto load_stage = [&](int s, int k0) {
        uint32_t a_base = smem_base + (uint32_t)s * GBM * A_STRIDE * 4;
        uint32_t b_base = bs_base + (uint32_t)s * GBK * B_STRIDE * 4;
#pragma unroll
        for (int j = 0; j < 4; j++) {
            int cch = tid + j * 256;
            int row = cch >> 3, kc = cch & 7;
            int gr = br + row;
            const float* src = x + (size_t)(gr < NN ? gr : 0) * IND + k0 + kc * 4;
            cpa16(a_base + (row * A_STRIDE + kc * 4) * 4, src, gr < NN ? 16 : 0);
        }
#pragma unroll
        for (int j = 0; j < 3; j++) {
            int cch = tid + j * 256;
            int row = cch / 24, seg = cch % 24;
            const float* src = g_wcat + (k0 + row) * NCOL + bc + seg * 4;
            cpa16(b_base + (row * B_STRIDE + seg * 4) * 4, src, 16);
        }
    };

    load_stage(0, 0);
    asm volatile("cp.async.commit_group;\n");

#pragma unroll
    for (int it = 0; it < 4; it++) {
        if (it < 3) {
            load_stage((it + 1) & 1, (it + 1) * GBK);
            asm volatile("cp.async.commit_group;\n");
            asm volatile("cp.async.wait_group 1;\n");
        } else {
            asm volatile("cp.async.wait_group 0;\n");
        }
        __syncthreads();

        const uint32_t* Ac = As + (it & 1) * GBM * A_STRIDE;
        const uint32_t* Bc = Bs + (it & 1) * GBK * B_STRIDE;
#pragma unroll
        for (int ks = 0; ks < 4; ks++) {
            int kb = ks * 8;
            uint32_t a[2][4];
#pragma unroll
            for (int mt = 0; mt < 2; mt++) {
                int r0 = warp_m * 32 + mt * 16 + gID;
                a[mt][0] = f2tf(__uint_as_float(Ac[r0 * A_STRIDE + kb + tig]));
                a[mt][1] = f2tf(__uint_as_float(Ac[(r0 + 8) * A_STRIDE + kb + tig]));
                a[mt][2] = f2tf(__uint_as_float(Ac[r0 * A_STRIDE + kb + tig + 4]));
                a[mt][3] = f2tf(__uint_as_float(Ac[(r0 + 8) * A_STRIDE + kb + tig + 4]));
            }
            uint32_t b[6][2];
#pragma unroll
            for (int nt = 0; nt < 6; nt++) {
                int col = warp_n * 48 + nt * 8 + gID;
                b[nt][0] = Bc[(kb + tig) * B_STRIDE + col];
                b[nt][1] = Bc[(kb + tig + 4) * B_STRIDE + col];
            }
#pragma unroll
            for (int mt = 0; mt < 2; mt++)
#pragma unroll
                for (int nt = 0; nt < 6; nt++)
                    asm volatile(
                        "mma.sync.aligned.m16n8k8.row.col.f32.tf32.tf32.f32 "
                        "{%0,%1,%2,%3}, {%4,%5,%6,%7}, {%8,%9}, {%0,%1,%2,%3};"
                        : "+f"(c[mt][nt][0]), "+f"(c[mt][nt][1]),
                          "+f"(c[mt][nt][2]), "+f"(c[mt][nt][3])
                        : "r"(a[mt][0]), "r"(a[mt][1]), "r"(a[mt][2]), "r"(a[mt][3]),
                          "r"(b[nt][0]), "r"(b[nt][1]));
        }
        __syncthreads();
    }

    // epilogue: write y1 as fp16
#pragma unroll
    for (int mt = 0; mt < 2; mt++) {
        int row0 = br + warp_m * 32 + mt * 16 + gID;
#pragma unroll
        for (int nt = 0; nt < 6; nt++) {
            int col = bc + warp_n * 48 + nt * 8 + 2 * tig;
            if (row0 < NN)
                *(__half2*)&g_y1h[(size_t)row0 * NCOL + col] =
                    __floats2half2_rn(c[mt][nt][0], c[mt][nt][1]);
            if (row0 + 8 < NN)
                *(__half2*)&g_y1h[(size_t)(row0 + 8) * NCOL + col] =
                    __floats2half2_rn(c[mt][nt][2], c[mt][nt][3]);
        }
    }
}

// -------- layer-1 scatter: LDG.128 fp16 gather + ONE red.v4.f16x2 per 8 feats --------
__global__ __launch_bounds__(256) void scatter1_kernel(const void* __restrict__ ei,
                                                       const void* __restrict__ et) {
    int t = blockIdx.x * blockDim.x + threadIdx.x;   // NE*4 threads exactly
    int e = t >> 2, c = t & 3;
    int src = edge_at(ei, e);
    int dst = edge_at(ei, (size_t)NE + e);
    int r   = edge_at(et, e);
    // 4 threads cover one 64B fp16 message: 16B (8 halfs) each
    uint4 v = *(const uint4*)&g_y1h[(size_t)src * NCOL + r * HID + c * 8];
    asm volatile("red.global.add.noftz.v4.f16x2 [%0], {%1,%2,%3,%4};"
                 :: "l"(&g_agg1h[dst * HID + c * 8]),
                    "r"(v.x), "r"(v.y), "r"(v.z), "r"(v.w) : "memory");
    if (c == 0) atomicAdd(&g_degi[dst], 1);
}

// -------- h = relu(agg1/deg + x@root1 + b1);  y2[n,r,:] = h[n] @ W2p[r] --------
__global__ __launch_bounds__(256) void h_y2_kernel(const float* __restrict__ b1) {
    __shared__ float sh[32][33];
    __shared__ float sw[512];
    int t = threadIdx.x;
    int n0 = blockIdx.x * 32;
    sw[t] = g_W2p[t];
    sw[t + 256] = g_W2p[t + 256];
#pragma unroll
    for (int j = 0; j < 4; j++) {
        int i = t + j * 256;
        int n_l = i >> 5, k = i & 31;
        int n = n0 + n_l;
        int di = g_degi[n];
        float sum = __half2float(g_agg1h[n * 32 + k]);
        float d = di > 1 ? (float)di : 1.f;
        float v = sum / d + __half2float(g_y1h[(size_t)n * NCOL + 256 + k]) + b1[k];
        v = v > 0.f ? v : 0.f;
        g_h[n * 32 + k] = v;
        sh[n_l][k] = v;
    }
    __syncthreads();
    int n_l = t >> 3, r = t & 7;
    float c0 = 0.f, c1 = 0.f;
#pragma unroll
    for (int k = 0; k < 32; k++) {
        float hv = sh[n_l][k];
        float2 w = *(const float2*)&sw[(r * 32 + k) * 2];
        c0 += hv * w.x;
        c1 += hv * w.y;
    }
    *(float2*)&g_y2[(n0 + n_l) * 16 + r * 2] = make_float2(c0, c1);
}

// -------- layer-2 scatter: one packed u64 atomic per edge --------
__global__ __launch_bounds__(256) void scatter2_kernel(const void* __restrict__ ei,
                                                       const void* __restrict__ et) {
    int e = blockIdx.x * blockDim.x + threadIdx.x;   // NE threads exactly
    int src = edge_at(ei, e);
    int dst = edge_at(ei, (size_t)NE + e);
    int r   = edge_at(et, e);
    float2 v = *(const float2*)&g_y2[src * 16 + r * 2];
    unsigned q0 = (unsigned)__float2int_rn(v.x * QSCALE) + QBIAS;
    unsigned q1 = (unsigned)__float2int_rn(v.y * QSCALE) + QBIAS;
    atomicAdd(&g_acc2q[dst], (unsigned long long)q0 | ((unsigned long long)q1 << 32));
}

// -------- out[n] = acc2[n]/deg + h[n] @ r2p + bp --------
__global__ __launch_bounds__(256) void out2_kernel(float* __restrict__ out) {
    int n = blockIdx.x * 256 + threadIdx.x;
    if (n >= NN) return;
    int di = g_degi[n];
    unsigned long long p = g_acc2q[n];
    float m0 = (float)(int)((unsigned)p - (unsigned)di * QBIAS) * QINV;
    float m1 = (float)(int)((unsigned)(p >> 32) - (unsigned)di * QBIAS) * QINV;
    float d = di > 1 ? (float)di : 1.f;
    float inv = 1.f / d;
    float c0 = m0 * inv;
    float c1 = m1 * inv;
#pragma unroll
    for (int k = 0; k < 32; k++) {
        float hv = g_h[n * 32 + k];
        c0 += hv * g_r2p[k * 2 + 0];
        c1 += hv * g_r2p[k * 2 + 1];
    }
    out[n * 2 + 0] = c0 + g_bp[0];
    out[n * 2 + 1] = c1 + g_bp[1];
}

extern "C" void kernel_launch(void* const* d_in, const int* in_sizes, int n_in,
                              void* d_out, int out_size) {
    const float* x     = (const float*)d_in[0];
    const void*  ei    = d_in[1];
    const void*  et    = d_in[2];
    const float* W1    = (const float*)d_in[3];
    const float* root1 = (const float*)d_in[4];
    const float* b1    = (const float*)d_in[5];
    const float* W2    = (const float*)d_in[6];
    const float* root2 = (const float*)d_in[7];
    const float* b2    = (const float*)d_in[8];
    const float* lin_w = (const float*)d_in[9];
    const float* lin_b = (const float*)d_in[10];
    float* out         = (float*)d_out;

    cudaFuncSetAttribute(gemm_tf32_kernel,
                         cudaFuncAttributeMaxDynamicSharedMemorySize, GEMM_SMEM);

    detect_kernel<<<1, 32>>>((const int*)ei);
    prep_kernel<<<145, 256>>>(W1, root1, W2, root2, b2, lin_w, lin_b);
    zero_kernel<<<2048, 256>>>();
    gemm_tf32_kernel<<<dim3((NN + GBM - 1) / GBM, NCOL / GBN), 256, GEMM_SMEM>>>(x);
    scatter1_kernel<<<(NE * 4) / 256, 256>>>(ei, et);
    h_y2_kernel<<<NN / 32, 256>>>(b1);
    scatter2_kernel<<<NE / 256, 256>>>(ei, et);
    out2_kernel<<<(NN + 255) / 256, 256>>>(out);
}

// round 15
// speedup vs baseline: 2.1971x; 1.0909x over previous
#include <cuda_runtime.h>
#include <cuda_fp16.h>
#include <cstdint>

#define NN 100000
#define NE 1600000
#define IND 128
#define HID 32
#define OUTD 64
#define NCOL 288   // 8*32 + 32 (root)

// layer-2 32-bit fixed point: lane = deg*2^24 + round(v*16384)
#define QSCALE 16384.0f
#define QINV   (1.0f / 16384.0f)
#define QBIAS  (1u << 24)

// -------- scratch (static device memory; 16B-aligned) --------
__device__ __align__(16) __half g_wcatT[NCOL * IND];            // fp16 weights, transposed [j][k]
__device__ __align__(16) __half g_xh[(size_t)NN * IND];         // fp16 x (25.6 MB)
__device__ __align__(16) __half g_y1h[(size_t)NN * NCOL];       // fp16 y1 (57 MB)
__device__ __align__(16) __half g_agg1h[NN * HID];              // fp16 accumulators (6.4 MB)
__device__ __align__(16) unsigned long long g_acc2q[NN];        // 32-bit×2 lanes
__device__ __align__(16) int g_degi[NN];
__device__ __align__(16) float g_h[NN * HID];
__device__ __align__(16) float g_y2[NN * 16];                   // [n][r][c]: h @ W2p
__device__ __align__(16) float g_W2p[512];
__device__ __align__(16) float g_r2p[64];
__device__ __align__(16) float g_bp[2];
__device__ int g_is64;

__global__ void detect_kernel(const int* __restrict__ ei_raw) {
    if (threadIdx.x == 0 && blockIdx.x == 0) {
        int is64 = 1;
        for (int i = 0; i < 1024; i++)
            if (ei_raw[2 * i + 1] != 0) { is64 = 0; break; }
        g_is64 = is64;
    }
}

__device__ __forceinline__ int edge_at(const void* __restrict__ p, size_t i) {
    if (g_is64) return (int)((const long long*)p)[i];
    return ((const int*)p)[i];
}

// -------- prep: pack fp16 transposed weights, fold classifier --------
__global__ void prep_kernel(const float* __restrict__ W1, const float* __restrict__ root1,
                            const float* __restrict__ W2, const float* __restrict__ root2,
                            const float* __restrict__ b2, const float* __restrict__ lin_w,
                            const float* __restrict__ lin_b) {
    int t = blockIdx.x * blockDim.x + threadIdx.x;
    int stride = gridDim.x * blockDim.x;
    for (int i = t; i < NCOL * IND; i += stride) {
        int j = i / IND, k = i % IND;
        float v;
        if (j < 256) v = W1[(j >> 5) * (IND * HID) + k * HID + (j & 31)];
        else         v = root1[k * HID + (j - 256)];
        g_wcatT[i] = __float2half(v);
    }
    if (t < 512) {
        int idx = t >> 1, c = t & 1;
        const float* wrow = W2 + idx * OUTD;
        float s = 0.f;
        for (int o = 0; o < OUTD; o++) s += wrow[o] * lin_w[o * 2 + c];
        g_W2p[t] = s;
    }
    if (t < 64) {
        int k = t >> 1, c = t & 1;
        float s = 0.f;
        for (int o = 0; o < OUTD; o++) s += root2[k * OUTD + o] * lin_w[o * 2 + c];
        g_r2p[t] = s;
    }
    if (t < 2) {
        float s = lin_b[t];
        for (int o = 0; o < OUTD; o++) s += b2[o] * lin_w[o * 2 + t];
        g_bp[t] = s;
    }
}

// -------- fused: zero accumulators + stage x to fp16 --------
__global__ void zero_kernel(const float* __restrict__ x) {
    int t = blockIdx.x * blockDim.x + threadIdx.x;
    int stride = gridDim.x * blockDim.x;
    float4 z = make_float4(0.f, 0.f, 0.f, 0.f);
    for (int i = t; i < NN * 4; i += stride)  ((float4*)g_agg1h)[i] = z;
    for (int i = t; i < NN / 2; i += stride)  ((float4*)g_acc2q)[i] = z;
    for (int i = t; i < NN / 4; i += stride)  ((float4*)g_degi)[i]  = z;
    __half2* xh2 = (__half2*)g_xh;
    for (int i = t; i < NN * 32; i += stride) {          // 4 floats -> 2 half2
        float4 v = ((const float4*)x)[i];
        xh2[i * 2 + 0] = __floats2half2_rn(v.x, v.y);
        xh2[i * 2 + 1] = __floats2half2_rn(v.z, v.w);
    }
}

// -------- fp16 tensor-core GEMM (cp.async double-buffered) --------
#define GBM 128
#define GBN 96
#define GBK 64
#define A_STRH 72                      // halves per A row (64 + 8 pad)
#define B_STRH 72
#define A_TILE_H (GBM * A_STRH)        // halves
#define B_TILE_H (GBN * B_STRH)
#define GEMM_SMEM ((2 * A_TILE_H + 2 * B_TILE_H) * 2)

__device__ __forceinline__ void cpa16(uint32_t dst_s, const void* src, int sz) {
    asm volatile("cp.async.ca.shared.global [%0], [%1], 16, %2;\n"
                 :: "r"(dst_s), "l"(src), "r"(sz));
}

__global__ __launch_bounds__(256) void gemm_f16_kernel() {
    extern __shared__ __half smem[];
    uint32_t smem_base = (uint32_t)__cvta_generic_to_shared(smem);
    uint32_t bs_base = smem_base + 2 * A_TILE_H * 2;

    int tid  = threadIdx.x;
    int lane = tid & 31, wid = tid >> 5;
    int warp_m = wid & 3, warp_n = wid >> 2;      // 4x2 warp grid
    int br = blockIdx.x * GBM;
    int bc = blockIdx.y * GBN;
    int gID = lane >> 2, tig = lane & 3;

    float c[2][6][4];
#pragma unroll
    for (int mt = 0; mt < 2; mt++)
#pragma unroll
        for (int nt = 0; nt < 6; nt++)
#pragma unroll
            for (int q = 0; q < 4; q++) c[mt][nt][q] = 0.f;

    auto load_stage = [&](int s, int k0) {
        uint32_t a_base = smem_base + (uint32_t)s * A_TILE_H * 2;
        uint32_t b_base = bs_base + (uint32_t)s * B_TILE_H * 2;
#pragma unroll
        for (int j = 0; j < 4; j++) {            // A: 128 rows x 8 chunks of 8 halves
            int cch = tid + j * 256;
            int row = cch >> 3, kc = cch & 7;
            int gr = br + row;
            const __half* src = g_xh + (size_t)(gr < NN ? gr : 0) * IND + k0 + kc * 8;
            cpa16(a_base + (row * A_STRH + kc * 8) * 2, src, gr < NN ? 16 : 0);
        }
#pragma unroll
        for (int j = 0; j < 3; j++) {            // B: 96 rows x 8 chunks
            int cch = tid + j * 256;
            int row = cch >> 3, kc = cch & 7;
            const __half* src = g_wcatT + (bc + row) * IND + k0 + kc * 8;
            cpa16(b_base + (row * B_STRH + kc * 8) * 2, src, 16);
        }
    };

    load_stage(0, 0);
    asm volatile("cp.async.commit_group;\n");

#pragma unroll
    for (int it = 0; it < 2; it++) {
        if (it < 1) {
            load_stage(1, GBK);
            asm volatile("cp.async.commit_group;\n");
            asm volatile("cp.async.wait_group 1;\n");
        } else {
            asm volatile("cp.async.wait_group 0;\n");
        }
        __syncthreads();

        const uint32_t* Ac = (const uint32_t*)(smem + (it & 1) * A_TILE_H);
        const uint32_t* Bc = (const uint32_t*)(smem + 2 * A_TILE_H + (it & 1) * B_TILE_H);
        // word strides: A_STRH/2 = 36, B_STRH/2 = 36
#pragma unroll
        for (int ks = 0; ks < 4; ks++) {
            int kw = ks * 8;                      // k offset in words (16 halves)
            uint32_t a[2][4];
#pragma unroll
            for (int mt = 0; mt < 2; mt++) {
                int r0 = warp_m * 32 + mt * 16 + gID;
                a[mt][0] = Ac[r0 * 36 + kw + tig];
                a[mt][1] = Ac[(r0 + 8) * 36 + kw + tig];
                a[mt][2] = Ac[r0 * 36 + kw + 4 + tig];
                a[mt][3] = Ac[(r0 + 8) * 36 + kw + 4 + tig];
            }
            uint32_t b[6][2];
#pragma unroll
            for (int nt = 0; nt < 6; nt++) {
                int col = warp_n * 48 + nt * 8 + gID;
                b[nt][0] = Bc[col * 36 + kw + tig];
                b[nt][1] = Bc[col * 36 + kw + 4 + tig];
            }
#pragma unroll
            for (int mt = 0; mt < 2; mt++)
#pragma unroll
                for (int nt = 0; nt < 6; nt++)
                    asm volatile(
                        "mma.sync.aligned.m16n8k16.row.col.f32.f16.f16.f32 "
                        "{%0,%1,%2,%3}, {%4,%5,%6,%7}, {%8,%9}, {%0,%1,%2,%3};"
                        : "+f"(c[mt][nt][0]), "+f"(c[mt][nt][1]),
                          "+f"(c[mt][nt][2]), "+f"(c[mt][nt][3])
                        : "r"(a[mt][0]), "r"(a[mt][1]), "r"(a[mt][2]), "r"(a[mt][3]),
                          "r"(b[nt][0]), "r"(b[nt][1]));
        }
        __syncthreads();
    }

    // epilogue: write y1 as fp16
#pragma unroll
    for (int mt = 0; mt < 2; mt++) {
        int row0 = br + warp_m * 32 + mt * 16 + gID;
#pragma unroll
        for (int nt = 0; nt < 6; nt++) {
            int col = bc + warp_n * 48 + nt * 8 + 2 * tig;
            if (row0 < NN)
                *(__half2*)&g_y1h[(size_t)row0 * NCOL + col] =
                    __floats2half2_rn(c[mt][nt][0], c[mt][nt][1]);
            if (row0 + 8 < NN)
                *(__half2*)&g_y1h[(size_t)(row0 + 8) * NCOL + col] =
                    __floats2half2_rn(c[mt][nt][2], c[mt][nt][3]);
        }
    }
}

// -------- layer-1 scatter: LDG.128 fp16 gather + red.v4.f16x2 --------
__global__ __launch_bounds__(256) void scatter1_kernel(const void* __restrict__ ei,
                                                       const void* __restrict__ et) {
    int t = blockIdx.x * blockDim.x + threadIdx.x;   // NE*4 threads exactly
    int e = t >> 2, c = t & 3;
    int src = edge_at(ei, e);
    int dst = edge_at(ei, (size_t)NE + e);
    int r   = edge_at(et, e);
    uint4 v = *(const uint4*)&g_y1h[(size_t)src * NCOL + r * HID + c * 8];
    asm volatile("red.global.add.noftz.v4.f16x2 [%0], {%1,%2,%3,%4};"
                 :: "l"(&g_agg1h[dst * HID + c * 8]),
                    "r"(v.x), "r"(v.y), "r"(v.z), "r"(v.w) : "memory");
    if (c == 0) atomicAdd(&g_degi[dst], 1);
}

// -------- h = relu(agg1/deg + x@root1 + b1);  y2[n,r,:] = h[n] @ W2p[r] --------
__global__ __launch_bounds__(256) void h_y2_kernel(const float* __restrict__ b1) {
    __shared__ float sh[32][33];
    __shared__ float sw[512];
    int t = threadIdx.x;
    int n0 = blockIdx.x * 32;
    sw[t] = g_W2p[t];
    sw[t + 256] = g_W2p[t + 256];
#pragma unroll
    for (int j = 0; j < 4; j++) {
        int i = t + j * 256;
        int n_l = i >> 5, k = i & 31;
        int n = n0 + n_l;
        int di = g_degi[n];
        float sum = __half2float(g_agg1h[n * 32 + k]);
        float d = di > 1 ? (float)di : 1.f;
        float v = sum / d + __half2float(g_y1h[(size_t)n * NCOL + 256 + k]) + b1[k];
        v = v > 0.f ? v : 0.f;
        g_h[n * 32 + k] = v;
        sh[n_l][k] = v;
    }
    __syncthreads();
    int n_l = t >> 3, r = t & 7;
    float c0 = 0.f, c1 = 0.f;
#pragma unroll
    for (int k = 0; k < 32; k++) {
        float hv = sh[n_l][k];
        float2 w = *(const float2*)&sw[(r * 32 + k) * 2];
        c0 += hv * w.x;
        c1 += hv * w.y;
    }
    *(float2*)&g_y2[(n0 + n_l) * 16 + r * 2] = make_float2(c0, c1);
}

// -------- layer-2 scatter: one packed u64 atomic per edge --------
__global__ __launch_bounds__(256) void scatter2_kernel(const void* __restrict__ ei,
                                                       const void* __restrict__ et) {
    int e = blockIdx.x * blockDim.x + threadIdx.x;   // NE threads exactly
    int src = edge_at(ei, e);
    int dst = edge_at(ei, (size_t)NE + e);
    int r   = edge_at(et, e);
    float2 v = *(const float2*)&g_y2[src * 16 + r * 2];
    unsigned q0 = (unsigned)__float2int_rn(v.x * QSCALE) + QBIAS;
    unsigned q1 = (unsigned)__float2int_rn(v.y * QSCALE) + QBIAS;
    atomicAdd(&g_acc2q[dst], (unsigned long long)q0 | ((unsigned long long)q1 << 32));
}

// -------- out[n] = acc2[n]/deg + h[n] @ r2p + bp --------
__global__ __launch_bounds__(256) void out2_kernel(float* __restrict__ out) {
    int n = blockIdx.x * 256 + threadIdx.x;
    if (n >= NN) return;
    int di = g_degi[n];
    unsigned long long p = g_acc2q[n];
    float m0 = (float)(int)((unsigned)p - (unsigned)di * QBIAS) * QINV;
    float m1 = (float)(int)((unsigned)(p >> 32) - (unsigned)di * QBIAS) * QINV;
    float d = di > 1 ? (float)di : 1.f;
    float inv = 1.f / d;
    float c0 = m0 * inv;
    float c1 = m1 * inv;
#pragma unroll
    for (int k = 0; k < 32; k++) {
        float hv = g_h[n * 32 + k];
        c0 += hv * g_r2p[k * 2 + 0];
        c1 += hv * g_r2p[k * 2 + 1];
    }
    out[n * 2 + 0] = c0 + g_bp[0];
    out[n * 2 + 1] = c1 + g_bp[1];
}

extern "C" void kernel_launch(void* const* d_in, const int* in_sizes, int n_in,
                              void* d_out, int out_size) {
    const float* x     = (const float*)d_in[0];
    const void*  ei    = d_in[1];
    const void*  et    = d_in[2];
    const float* W1    = (const float*)d_in[3];
    const float* root1 = (const float*)d_in[4];
    const float* b1    = (const float*)d_in[5];
    const float* W2    = (const float*)d_in[6];
    const float* root2 = (const float*)d_in[7];
    const float* b2    = (const float*)d_in[8];
    const float* lin_w = (const float*)d_in[9];
    const float* lin_b = (const float*)d_in[10];
    float* out         = (float*)d_out;

    cudaFuncSetAttribute(gemm_f16_kernel,
                         cudaFuncAttributeMaxDynamicSharedMemorySize, GEMM_SMEM);

    detect_kernel<<<1, 32>>>((const int*)ei);
    prep_kernel<<<145, 256>>>(W1, root1, W2, root2, b2, lin_w, lin_b);
    zero_kernel<<<4096, 256>>>(x);
    gemm_f16_kernel<<<dim3((NN + GBM - 1) / GBM, NCOL / GBN), 256, GEMM_SMEM>>>();
    scatter1_kernel<<<(NE * 4) / 256, 256>>>(ei, et);
    h_y2_kernel<<<NN / 32, 256>>>(b1);
    scatter2_kernel<<<NE / 256, 256>>>(ei, et);
    out2_kernel<<<(NN + 255) / 256, 256>>>(out);
}